// round 1
// baseline (speedup 1.0000x reference)
#include <cuda_runtime.h>
#include <cuda_bf16.h>
#include <cstdint>

// Scratch for per-vertex valence counts. 4M floats = 16 MB static, covers any
// plausible shape variant (reference uses V = 1,000,000).
__device__ float g_valence[4u << 20];

// -----------------------------------------------------------------------------
// Scatter: one thread handles 4 consecutive features of one edge.
//   idx = e*8 + s, s in [0,8): thread covers x[e][4s..4s+3].
// Loads are perfectly coalesced float4 (warp = 4 edges x 512B contiguous).
// Accumulation via 128-bit vector RED (red.global.add.v4.f32, sm_90+),
// 4x fewer RED ops than scalar atomicAdd. Valence via one scalar RED per edge.
// -----------------------------------------------------------------------------
__global__ void scatter_kernel(const float4* __restrict__ x4,
                               const int* __restrict__ vertex_ids,
                               float* __restrict__ out,
                               long long total_quads)  // n_he * 8
{
    long long idx = (long long)blockIdx.x * blockDim.x + threadIdx.x;
    long long stride = (long long)gridDim.x * blockDim.x;
    for (; idx < total_quads; idx += stride) {
        long long e = idx >> 3;
        int s = (int)(idx & 7);
        int vid = __ldg(vertex_ids + e);

        float4 v = x4[idx];  // x is row-major [n_he][32] -> quad idx maps directly

        float* dst = out + (long long)vid * 32 + s * 4;  // 16B aligned
        asm volatile("red.global.add.v4.f32 [%0], {%1, %2, %3, %4};"
                     :: "l"(dst), "f"(v.x), "f"(v.y), "f"(v.z), "f"(v.w)
                     : "memory");

        if (s == 0) {
            atomicAdd(&g_valence[vid], 1.0f);  // compiles to RED (result unused)
        }
    }
}

// -----------------------------------------------------------------------------
// Epilogue: out[v][:] /= max(valence[v], 1). One thread per float4.
// -----------------------------------------------------------------------------
__global__ void divide_kernel(float4* __restrict__ out4,
                              long long total_quads)  // n_vertices * 8
{
    long long idx = (long long)blockIdx.x * blockDim.x + threadIdx.x;
    long long stride = (long long)gridDim.x * blockDim.x;
    for (; idx < total_quads; idx += stride) {
        long long vtx = idx >> 3;
        float val = g_valence[vtx];
        float inv = 1.0f / fmaxf(val, 1.0f);
        float4 o = out4[idx];
        o.x *= inv; o.y *= inv; o.z *= inv; o.w *= inv;
        out4[idx] = o;
    }
}

extern "C" void kernel_launch(void* const* d_in, const int* in_sizes, int n_in,
                              void* d_out, int out_size)
{
    const float4* x4        = (const float4*)d_in[0];
    const int*    vertex_ids = (const int*)d_in[1];
    // d_in[2] holds n_vertices on device; derive V from out_size instead
    // (no sync copies allowed under graph capture).

    long long n_he = in_sizes[1];                 // element count of vertex_ids
    long long V    = (long long)out_size / 32;    // [V, 32] output

    float* out = (float*)d_out;

    // Zero the accumulators (d_out is poisoned to 0xAA before timing).
    cudaMemsetAsync(d_out, 0, (size_t)out_size * sizeof(float));
    void* valence_ptr = nullptr;
    cudaGetSymbolAddress(&valence_ptr, g_valence);
    cudaMemsetAsync(valence_ptr, 0, (size_t)V * sizeof(float));

    // Scatter pass
    {
        long long total = n_he * 8;
        int threads = 256;
        long long blocks = (total + threads - 1) / threads;
        if (blocks > 0x7FFFFFFFLL) blocks = 0x7FFFFFFFLL;
        scatter_kernel<<<(unsigned)blocks, threads>>>(x4, vertex_ids, out, total);
    }

    // Divide pass
    {
        long long total = V * 8;
        int threads = 256;
        long long blocks = (total + threads - 1) / threads;
        divide_kernel<<<(unsigned)blocks, threads>>>((float4*)d_out, total);
    }
}